// round 14
// baseline (speedup 1.0000x reference)
#include <cuda_runtime.h>
#include <cuda_bf16.h>
#include <cuda_fp16.h>
#include <math.h>
#include <stdint.h>

#define Nn   65536
#define Ee   262144
#define Bb   2048
#define Hh   4
#define Dd   192
#define HIDD 768
#define Ll   2
#define E2   (Ee + Nn)
#define EPSC 1e-5f
#define SLOPE 0.2f

// ---------------- scratch (no allocations allowed) ----------------
__device__ __align__(128) __half g_hh[(size_t)Nn * HIDD];    // running node feats, fp16
__device__ __align__(128) __half g_xwh[(size_t)Nn * HIDD];   // projected feats, fp16
__device__ __align__(16) float g_asrc[2][Nn * Hh];
__device__ __align__(16) float g_adst[2][Nn * Hh];
__device__ int   g_cnt[Nn];
__device__ int   g_rowptr[Nn + 1];
__device__ int   g_cursor[Nn];
__device__ int   g_srcs[E2];
__device__ int   g_blk[64];
__device__ int   g_blkoff[64];
__device__ __align__(128) __half g_hgh[Bb * HIDD];
__device__ __align__(128) __half g_wth[(size_t)Ll * HIDD * HIDD];
__device__ __align__(128) __half g_owh[(size_t)HIDD * HIDD];

// ================= helpers =================
__device__ __forceinline__ uint32_t smem_to_u32(const void* smem_ptr) {
    uint32_t addr;
    asm("{ .reg .u64 tmp; cvta.to.shared.u64 tmp, %1; cvt.u32.u64 %0, tmp; }"
        : "=r"(addr) : "l"(smem_ptr));
    return addr;
}
__device__ __forceinline__ void ldsm_x4(uint32_t* r, uint32_t addr) {
    asm volatile("ldmatrix.sync.aligned.m8n8.x4.shared.b16 {%0,%1,%2,%3}, [%4];"
        : "=r"(r[0]), "=r"(r[1]), "=r"(r[2]), "=r"(r[3]) : "r"(addr));
}
__device__ __forceinline__ void mma_f16(float* c, const uint32_t* a, const uint32_t* b) {
    asm volatile("mma.sync.aligned.m16n8k16.row.col.f32.f16.f16.f32 "
        "{%0,%1,%2,%3},{%4,%5,%6,%7},{%8,%9},{%0,%1,%2,%3};"
        : "+f"(c[0]), "+f"(c[1]), "+f"(c[2]), "+f"(c[3])
        : "r"(a[0]), "r"(a[1]), "r"(a[2]), "r"(a[3]), "r"(b[0]), "r"(b[1]));
}
__device__ __forceinline__ void cp16(uint32_t saddr, const void* gaddr) {
    asm volatile("cp.async.cg.shared.global [%0], [%1], 16;" :: "r"(saddr), "l"(gaddr));
}
__device__ __forceinline__ uint32_t pack_half2(float a, float b) {
    __half ha = __float2half_rn(a), hb = __float2half_rn(b);
    return ((uint32_t)__half_as_ushort(hb) << 16) | __half_as_ushort(ha);
}

// ---------------- init: h = fp16(x) ----------------
__global__ void copy_x_split_kernel(const float* __restrict__ x) {
    size_t i = (size_t)blockIdx.x * blockDim.x + threadIdx.x;
    size_t n4 = (size_t)Nn * HIDD / 4;
    if (i >= n4) return;
    float4 v = ((const float4*)x)[i];
    uint2 hv;
    hv.x = pack_half2(v.x, v.y);
    hv.y = pack_half2(v.z, v.w);
    ((uint2*)g_hh)[i] = hv;
}

__global__ void deg_init_kernel() {
    int i = blockIdx.x * blockDim.x + threadIdx.x;
    if (i < Nn) g_cnt[i] = 1;   // self loop
}

// zero one alpha buffer (idx selects)
__global__ void zero_alpha_kernel(int which) {
    int i = blockIdx.x * blockDim.x + threadIdx.x;
    if (i < Nn) {
        float4 z = make_float4(0.f, 0.f, 0.f, 0.f);
        ((float4*)g_asrc[which])[i] = z;
        ((float4*)g_adst[which])[i] = z;
    }
}

__global__ void deg_count_kernel(const int* __restrict__ dstE) {
    int e = blockIdx.x * blockDim.x + threadIdx.x;
    if (e < Ee) atomicAdd(&g_cnt[dstE[e]], 1);
}

// ---------------- parallel scan: 3 tiny kernels ----------------
__global__ void scanA_kernel() {
    int tid = threadIdx.x;
    int i = blockIdx.x * 1024 + tid;
    int v = g_cnt[i];
    int lane = tid & 31, w = tid >> 5;
    int x = v;
    #pragma unroll
    for (int o = 1; o < 32; o <<= 1) {
        int y = __shfl_up_sync(0xffffffffu, x, o);
        if (lane >= o) x += y;
    }
    __shared__ int ws[32];
    if (lane == 31) ws[w] = x;
    __syncthreads();
    if (w == 0) {
        int s = ws[lane];
        #pragma unroll
        for (int o = 1; o < 32; o <<= 1) {
            int y = __shfl_up_sync(0xffffffffu, s, o);
            if (lane >= o) s += y;
        }
        ws[lane] = s;
    }
    __syncthreads();
    int incl = x + (w ? ws[w - 1] : 0);
    g_rowptr[i] = incl - v;
    if (tid == 1023) g_blk[blockIdx.x] = incl;
}
__global__ void scanB_kernel() {
    int tid = threadIdx.x;   // 64 threads
    int v = g_blk[tid];
    __shared__ int sh[64];
    sh[tid] = v;
    __syncthreads();
    for (int o = 1; o < 64; o <<= 1) {
        int t = (tid >= o) ? sh[tid - o] : 0;
        __syncthreads();
        sh[tid] += t;
        __syncthreads();
    }
    g_blkoff[tid] = sh[tid] - v;
    if (tid == 63) g_rowptr[Nn] = E2;
}
__global__ void scanC_kernel() {
    int i = blockIdx.x * 1024 + threadIdx.x;
    int r = g_rowptr[i] + g_blkoff[blockIdx.x];
    g_rowptr[i] = r;
    g_cursor[i] = r;
}

__global__ void fill_kernel(const int* __restrict__ srcE, const int* __restrict__ dstE) {
    int e = blockIdx.x * blockDim.x + threadIdx.x;
    if (e < Ee) {
        int d = dstE[e];
        int p = atomicAdd(&g_cursor[d], 1);
        g_srcs[p] = srcE[e];
    } else if (e < E2) {
        int i = e - Ee;
        int p = atomicAdd(&g_cursor[i], 1);
        g_srcs[p] = i;   // self loop
    }
}

// W -> fp16, transposed per HIDDxHIDD block: [k][n] -> [n][k]
__global__ void wt_prep_kernel(const float* __restrict__ W, __half* __restrict__ dst,
                               int total) {
    int i = blockIdx.x * blockDim.x + threadIdx.x;
    if (i >= total) return;
    int l = i / (HIDD * HIDD);
    int r = i % (HIDD * HIDD);
    int k = r / HIDD;
    int n = r % HIDD;
    dst[((size_t)l * HIDD + n) * HIDD + k] = __float2half_rn(W[i]);
}

// ---------------- fp16 tensor-core GEMM + fused alpha, fp16 C ----------------
#define KCH   96
#define ROWE  104
#define TILE_B (128 * ROWE * 2)             // 26624
#define GEMM_SMEM (2 * 2 * TILE_B)          // 106496 B

__device__ __forceinline__ void load_chunk(
    const __half* const* srcs, uint32_t sbase, int ch, int s, int tid)
{
    int kb = ch * KCH;
    #pragma unroll
    for (int t = 0; t < 2; t++) {
        const char* src = (const char*)srcs[t] + (size_t)kb * 2;
        uint32_t dstb = sbase + (uint32_t)(s * 2 + t) * TILE_B;
        #pragma unroll
        for (int it = 0; it < 6; it++) {
            int idx = it * 256 + tid;
            int row = idx / 12;
            int c   = idx % 12;
            uint32_t sa = dstb + row * (ROWE * 2) + c * 16;
            const char* ga = src + (size_t)row * (HIDD * 2) + c * 16;
            cp16(sa, ga);
        }
    }
    asm volatile("cp.async.commit_group;" ::: "memory");
}

__global__ void __launch_bounds__(256, 2) gemm_mma_kernel(
    const __half* __restrict__ Bh_l,
    __half* __restrict__ C,
    const float* __restrict__ asv, const float* __restrict__ adv,
    float* __restrict__ gas, float* __restrict__ gad)
{
    extern __shared__ __half smem[];
    const int tid = threadIdx.x;
    const int wid = tid >> 5, lane = tid & 31;
    const int m0 = blockIdx.y * 128, n0 = blockIdx.x * 128;
    const int wm = (wid >> 2) * 64;
    const int wn = (wid & 3) * 32;
    uint32_t sbase = smem_to_u32(smem);

    const __half* srcs[2] = {
        g_hh + (size_t)m0 * HIDD,
        Bh_l + (size_t)n0 * HIDD };

    float acc[4][4][4];
    #pragma unroll
    for (int mi = 0; mi < 4; mi++)
        #pragma unroll
        for (int ni = 0; ni < 4; ni++)
            #pragma unroll
            for (int j = 0; j < 4; j++) acc[mi][ni][j] = 0.f;

    load_chunk(srcs, sbase, 0, 0, tid);

    uint32_t b_lrow = (lane & 7) + ((lane >> 4) << 3);
    uint32_t b_lcol = ((lane >> 3) & 1) << 3;

    for (int ch = 0; ch < 8; ch++) {
        int s = ch & 1;
        asm volatile("cp.async.wait_group 0;" ::: "memory");
        __syncthreads();
        if (ch < 7) load_chunk(srcs, sbase, ch + 1, s ^ 1, tid);

        uint32_t a_b  = sbase + (uint32_t)(s * 2 + 0) * TILE_B;
        uint32_t bh_b = sbase + (uint32_t)(s * 2 + 1) * TILE_B;

        #pragma unroll
        for (int ks = 0; ks < 6; ks++) {
            int kk = ks * 16;
            uint32_t Af[4][4], Bh4[2][4];
            uint32_t aoff = (uint32_t)(wm + (lane & 15)) * (ROWE * 2)
                          + (uint32_t)(kk + 8 * (lane >> 4)) * 2;
            uint32_t boff = (uint32_t)(wn + b_lrow) * (ROWE * 2)
                          + (uint32_t)(kk + b_lcol) * 2;
            #pragma unroll
            for (int nb = 0; nb < 2; nb++)
                ldsm_x4(Bh4[nb], bh_b + boff + nb * 16 * (ROWE * 2));
            #pragma unroll
            for (int mi = 0; mi < 4; mi++)
                ldsm_x4(Af[mi], a_b + aoff + mi * 16 * (ROWE * 2));
            #pragma unroll
            for (int mi = 0; mi < 4; mi++)
                #pragma unroll
                for (int ni = 0; ni < 4; ni++)
                    mma_f16(acc[mi][ni], Af[mi], &Bh4[ni >> 1][(ni & 1) * 2]);
        }
    }

    int gid = lane >> 2, tig = lane & 3;

    // ---- write C (fp16) ----
    #pragma unroll
    for (int mi = 0; mi < 4; mi++) {
        int r0 = m0 + wm + mi * 16 + gid;
        #pragma unroll
        for (int ni = 0; ni < 4; ni++) {
            int col = n0 + wn + ni * 8 + tig * 2;
            *(uint32_t*)&C[(size_t)r0 * HIDD + col] =
                pack_half2(acc[mi][ni][0], acc[mi][ni][1]);
            *(uint32_t*)&C[(size_t)(r0 + 8) * HIDD + col] =
                pack_half2(acc[mi][ni][2], acc[mi][ni][3]);
        }
    }

    // ---- fused alpha partials (fp32 acc) ----
    int head = (n0 + wn) / Dd;
    float as_c[4][2], ad_c[4][2];
    #pragma unroll
    for (int ni = 0; ni < 4; ni++) {
        int gc = n0 + wn + ni * 8 + tig * 2;
        as_c[ni][0] = asv[gc]; as_c[ni][1] = asv[gc + 1];
        ad_c[ni][0] = adv[gc]; ad_c[ni][1] = adv[gc + 1];
    }
    #pragma unroll
    for (int mi = 0; mi < 4; mi++) {
        #pragma unroll
        for (int half = 0; half < 2; half++) {
            float ps = 0.f, pd = 0.f;
            #pragma unroll
            for (int ni = 0; ni < 4; ni++) {
                float c0 = acc[mi][ni][half * 2 + 0];
                float c1 = acc[mi][ni][half * 2 + 1];
                ps += c0 * as_c[ni][0] + c1 * as_c[ni][1];
                pd += c0 * ad_c[ni][0] + c1 * ad_c[ni][1];
            }
            ps += __shfl_xor_sync(0xffffffffu, ps, 1);
            ps += __shfl_xor_sync(0xffffffffu, ps, 2);
            pd += __shfl_xor_sync(0xffffffffu, pd, 1);
            pd += __shfl_xor_sync(0xffffffffu, pd, 2);
            if (tig == 0) {
                int r = m0 + wm + mi * 16 + gid + half * 8;
                atomicAdd(&gas[r * Hh + head], ps);
                atomicAdd(&gad[r * Hh + head], pd);
            }
        }
    }
}

// ---------------- fp16 tensor GEMM for final projection ----------------
__global__ void __launch_bounds__(256, 2) gemm_out_kernel(
    float* __restrict__ Cout, const float* __restrict__ ob)
{
    extern __shared__ __half smem[];
    const int tid = threadIdx.x;
    const int wid = tid >> 5, lane = tid & 31;
    const int m0 = blockIdx.y * 128, n0 = blockIdx.x * 128;
    const int wm = (wid >> 2) * 64;
    const int wn = (wid & 3) * 32;
    uint32_t sbase = smem_to_u32(smem);

    const __half* srcs[2] = {
        g_hgh + (size_t)m0 * HIDD,
        g_owh + (size_t)n0 * HIDD };

    float acc[4][4][4];
    #pragma unroll
    for (int mi = 0; mi < 4; mi++)
        #pragma unroll
        for (int ni = 0; ni < 4; ni++)
            #pragma unroll
            for (int j = 0; j < 4; j++) acc[mi][ni][j] = 0.f;

    load_chunk(srcs, sbase, 0, 0, tid);

    uint32_t b_lrow = (lane & 7) + ((lane >> 4) << 3);
    uint32_t b_lcol = ((lane >> 3) & 1) << 3;

    for (int ch = 0; ch < 8; ch++) {
        int s = ch & 1;
        asm volatile("cp.async.wait_group 0;" ::: "memory");
        __syncthreads();
        if (ch < 7) load_chunk(srcs, sbase, ch + 1, s ^ 1, tid);

        uint32_t a_b  = sbase + (uint32_t)(s * 2 + 0) * TILE_B;
        uint32_t bh_b = sbase + (uint32_t)(s * 2 + 1) * TILE_B;

        #pragma unroll
        for (int ks = 0; ks < 6; ks++) {
            int kk = ks * 16;
            uint32_t Af[4][4], Bh4[2][4];
            uint32_t aoff = (uint32_t)(wm + (lane & 15)) * (ROWE * 2)
                          + (uint32_t)(kk + 8 * (lane >> 4)) * 2;
            uint32_t boff = (uint32_t)(wn + b_lrow) * (ROWE * 2)
                          + (uint32_t)(kk + b_lcol) * 2;
            #pragma unroll
            for (int nb = 0; nb < 2; nb++)
                ldsm_x4(Bh4[nb], bh_b + boff + nb * 16 * (ROWE * 2));
            #pragma unroll
            for (int mi = 0; mi < 4; mi++)
                ldsm_x4(Af[mi], a_b + aoff + mi * 16 * (ROWE * 2));
            #pragma unroll
            for (int mi = 0; mi < 4; mi++)
                #pragma unroll
                for (int ni = 0; ni < 4; ni++)
                    mma_f16(acc[mi][ni], Af[mi], &Bh4[ni >> 1][(ni & 1) * 2]);
        }
    }

    int gid = lane >> 2, tig = lane & 3;
    #pragma unroll
    for (int mi = 0; mi < 4; mi++) {
        int r0 = m0 + wm + mi * 16 + gid;
        #pragma unroll
        for (int ni = 0; ni < 4; ni++) {
            int col = n0 + wn + ni * 8 + tig * 2;
            float b0 = ob[col], b1 = ob[col + 1];
            float2 v0 = make_float2(acc[mi][ni][0] + b0, acc[mi][ni][1] + b1);
            float2 v1 = make_float2(acc[mi][ni][2] + b0, acc[mi][ni][3] + b1);
            *(float2*)&Cout[(size_t)r0 * HIDD + col] = v0;
            *(float2*)&Cout[(size_t)(r0 + 8) * HIDD + col] = v1;
        }
    }
}

__device__ __forceinline__ float leaky(float v) {
    return v > 0.f ? v : SLOPE * v;
}

// per-edge contribution for agg (computes weights + accumulates)
struct EdgeW { float w0, w1, w2, w3; };
__device__ __forceinline__ EdgeW edge_w(const float* asrc, int s, float4 ad) {
    float4 as = *(const float4*)(asrc + s * 4);
    EdgeW e;
    e.w0 = __expf(leaky(as.x + ad.x));
    e.w1 = __expf(leaky(as.y + ad.y));
    e.w2 = __expf(leaky(as.z + ad.z));
    e.w3 = __expf(leaky(as.w + ad.w));
    return e;
}

// ---------------- single-pass fused GAT agg + bias + LN + ReLU + residual ----------------
__global__ void agg_fused_kernel(const float* __restrict__ bias,
                                 const float* __restrict__ gamma,
                                 const float* __restrict__ beta,
                                 const float* __restrict__ asrc,
                                 const float* __restrict__ adstv,
                                 const __half* __restrict__ xw)
{
    int w = (blockIdx.x * blockDim.x + threadIdx.x) >> 5;
    int lane = threadIdx.x & 31;
    if (w >= Nn) return;
    int beg = g_rowptr[w];
    int end = g_rowptr[w + 1];
    float4 ad = *(const float4*)(adstv + w * 4);
    bool s0 = lane < 24;
    bool s1 = lane < 16;
    bool s2 = lane < 8;

    float d0 = 0.f, d1 = 0.f, d2 = 0.f, d3 = 0.f;
    float2 acc2[3][4];
    #pragma unroll
    for (int j = 0; j < 3; j++)
        #pragma unroll
        for (int q = 0; q < 4; q++) acc2[j][q] = make_float2(0.f, 0.f);

    int e = beg;
    // 2-edge unrolled main loop for MLP
    for (; e + 1 < end; e += 2) {
        int sa = g_srcs[e], sb = g_srcs[e + 1];
        EdgeW ea = edge_w(asrc, sa, ad);
        EdgeW eb = edge_w(asrc, sb, ad);
        const uint4* xra = ((const uint4*)(xw + (size_t)sa * HIDD)) + lane;
        const uint4* xrb = ((const uint4*)(xw + (size_t)sb * HIDD)) + lane;
        d0 += ea.w0 + eb.w0; d1 += ea.w1 + eb.w1;
        d2 += ea.w2 + eb.w2; d3 += ea.w3 + eb.w3;
        float wsa[3], wsb[3];
        wsa[0] = s0 ? ea.w0 : ea.w1; wsb[0] = s0 ? eb.w0 : eb.w1;
        wsa[1] = s1 ? ea.w1 : ea.w2; wsb[1] = s1 ? eb.w1 : eb.w2;
        wsa[2] = s2 ? ea.w2 : ea.w3; wsb[2] = s2 ? eb.w2 : eb.w3;
        #pragma unroll
        for (int j = 0; j < 3; j++) {
            uint4 va = xra[j * 32];
            uint4 vb = xrb[j * 32];
            float2 a0 = __half22float2(*(const __half2*)&va.x);
            float2 a1 = __half22float2(*(const __half2*)&va.y);
            float2 a2 = __half22float2(*(const __half2*)&va.z);
            float2 a3 = __half22float2(*(const __half2*)&va.w);
            float2 b0 = __half22float2(*(const __half2*)&vb.x);
            float2 b1 = __half22float2(*(const __half2*)&vb.y);
            float2 b2 = __half22float2(*(const __half2*)&vb.z);
            float2 b3 = __half22float2(*(const __half2*)&vb.w);
            float wa = wsa[j], wb = wsb[j];
            acc2[j][0].x = fmaf(wa, a0.x, fmaf(wb, b0.x, acc2[j][0].x));
            acc2[j][0].y = fmaf(wa, a0.y, fmaf(wb, b0.y, acc2[j][0].y));
            acc2[j][1].x = fmaf(wa, a1.x, fmaf(wb, b1.x, acc2[j][1].x));
            acc2[j][1].y = fmaf(wa, a1.y, fmaf(wb, b1.y, acc2[j][1].y));
            acc2[j][2].x = fmaf(wa, a2.x, fmaf(wb, b2.x, acc2[j][2].x));
            acc2[j][2].y = fmaf(wa, a2.y, fmaf(wb, b2.y, acc2[j][2].y));
            acc2[j][3].x = fmaf(wa, a3.x, fmaf(wb, b3.x, acc2[j][3].x));
            acc2[j][3].y = fmaf(wa, a3.y, fmaf(wb, b3.y, acc2[j][3].y));
        }
    }
    if (e < end) {
        int sa = g_srcs[e];
        EdgeW ea = edge_w(asrc, sa, ad);
        d0 += ea.w0; d1 += ea.w1; d2 += ea.w2; d3 += ea.w3;
        float wsa[3];
        wsa[0] = s0 ? ea.w0 : ea.w1;
        wsa[1] = s1 ? ea.w1 : ea.w2;
        wsa[2] = s2 ? ea.w2 : ea.w3;
        const uint4* xra = ((const uint4*)(xw + (size_t)sa * HIDD)) + lane;
        #pragma unroll
        for (int j = 0; j < 3; j++) {
            uint4 va = xra[j * 32];
            float2 a0 = __half22float2(*(const __half2*)&va.x);
            float2 a1 = __half22float2(*(const __half2*)&va.y);
            float2 a2 = __half22float2(*(const __half2*)&va.z);
            float2 a3 = __half22float2(*(const __half2*)&va.w);
            float wa = wsa[j];
            acc2[j][0].x = fmaf(wa, a0.x, acc2[j][0].x);
            acc2[j][0].y = fmaf(wa, a0.y, acc2[j][0].y);
            acc2[j][1].x = fmaf(wa, a1.x, acc2[j][1].x);
            acc2[j][1].y = fmaf(wa, a1.y, acc2[j][1].y);
            acc2[j][2].x = fmaf(wa, a2.x, acc2[j][2].x);
            acc2[j][2].y = fmaf(wa, a2.y, acc2[j][2].y);
            acc2[j][3].x = fmaf(wa, a3.x, acc2[j][3].x);
            acc2[j][3].y = fmaf(wa, a3.y, acc2[j][3].y);
        }
    }

    float r0 = 1.f / d0, r1 = 1.f / d1, r2 = 1.f / d2, r3 = 1.f / d3;
    float rsel[3];
    rsel[0] = s0 ? r0 : r1;
    rsel[1] = s1 ? r1 : r2;
    rsel[2] = s2 ? r2 : r3;

    float s = 0.f, sq = 0.f;
    #pragma unroll
    for (int j = 0; j < 3; j++) {
        int fb = j * 64 + lane * 2;
        float4 b40 = ((const float4*)bias)[fb];
        float4 b41 = ((const float4*)bias)[fb + 1];
        float rr = rsel[j];
        acc2[j][0].x = fmaf(acc2[j][0].x, rr, b40.x);
        acc2[j][0].y = fmaf(acc2[j][0].y, rr, b40.y);
        acc2[j][1].x = fmaf(acc2[j][1].x, rr, b40.z);
        acc2[j][1].y = fmaf(acc2[j][1].y, rr, b40.w);
        acc2[j][2].x = fmaf(acc2[j][2].x, rr, b41.x);
        acc2[j][2].y = fmaf(acc2[j][2].y, rr, b41.y);
        acc2[j][3].x = fmaf(acc2[j][3].x, rr, b41.z);
        acc2[j][3].y = fmaf(acc2[j][3].y, rr, b41.w);
        #pragma unroll
        for (int q = 0; q < 4; q++) {
            s += acc2[j][q].x + acc2[j][q].y;
            sq = fmaf(acc2[j][q].x, acc2[j][q].x, sq);
            sq = fmaf(acc2[j][q].y, acc2[j][q].y, sq);
        }
    }
    #pragma unroll
    for (int o = 16; o; o >>= 1) {
        s  += __shfl_xor_sync(0xffffffffu, s, o);
        sq += __shfl_xor_sync(0xffffffffu, sq, o);
    }
    float mean = s * (1.f / HIDD);
    float var = sq * (1.f / HIDD) - mean * mean;
    float r = rsqrtf(var + EPSC);
    size_t base8 = (size_t)w * (HIDD / 8);
    #pragma unroll
    for (int j = 0; j < 3; j++) {
        int fb = j * 64 + lane * 2;
        size_t idx8 = base8 + j * 32 + lane;
        uint4 hprev = ((const uint4*)g_hh)[idx8];
        float2 h0 = __half22float2(*(const __half2*)&hprev.x);
        float2 h1 = __half22float2(*(const __half2*)&hprev.y);
        float2 h2 = __half22float2(*(const __half2*)&hprev.z);
        float2 h3 = __half22float2(*(const __half2*)&hprev.w);
        float4 g40 = ((const float4*)gamma)[fb];
        float4 g41 = ((const float4*)gamma)[fb + 1];
        float4 be0 = ((const float4*)beta)[fb];
        float4 be1 = ((const float4*)beta)[fb + 1];
        float y0 = fmaxf((acc2[j][0].x - mean) * r * g40.x + be0.x, 0.f) + h0.x;
        float y1 = fmaxf((acc2[j][0].y - mean) * r * g40.y + be0.y, 0.f) + h0.y;
        float y2 = fmaxf((acc2[j][1].x - mean) * r * g40.z + be0.z, 0.f) + h1.x;
        float y3 = fmaxf((acc2[j][1].y - mean) * r * g40.w + be0.w, 0.f) + h1.y;
        float y4 = fmaxf((acc2[j][2].x - mean) * r * g41.x + be1.x, 0.f) + h2.x;
        float y5 = fmaxf((acc2[j][2].y - mean) * r * g41.y + be1.y, 0.f) + h2.y;
        float y6 = fmaxf((acc2[j][3].x - mean) * r * g41.z + be1.z, 0.f) + h3.x;
        float y7 = fmaxf((acc2[j][3].y - mean) * r * g41.w + be1.w, 0.f) + h3.y;
        uint4 hv;
        hv.x = pack_half2(y0, y1);
        hv.y = pack_half2(y2, y3);
        hv.z = pack_half2(y4, y5);
        hv.w = pack_half2(y6, y7);
        ((uint4*)g_hh)[idx8] = hv;
    }
}

// ---------------- mean pool per graph (batch_vec sorted), fp16 in/out ----------------
__device__ __forceinline__ int lowerb(const int* a, int n, int key) {
    int lo = 0, hi = n;
    while (lo < hi) {
        int mid = (lo + hi) >> 1;
        if (a[mid] < key) lo = mid + 1; else hi = mid;
    }
    return lo;
}

__global__ void pool_kernel(const int* __restrict__ batch)
{
    int b = blockIdx.x;
    int tid = threadIdx.x;   // 256 threads
    __shared__ int s_beg, s_end;
    if (tid == 0) {
        s_beg = lowerb(batch, Nn, b);
        s_end = lowerb(batch, Nn, b + 1);
    }
    __syncthreads();
    int beg = s_beg, end = s_end;
    float a0 = 0.f, a1 = 0.f, a2 = 0.f;
    for (int n = beg; n < end; n++) {
        const __half* row = g_hh + (size_t)n * HIDD;
        a0 += __half2float(row[tid]);
        a1 += __half2float(row[256 + tid]);
        a2 += __half2float(row[512 + tid]);
    }
    float c = fmaxf((float)(end - beg), 1.0f);
    float inv = 1.f / c;
    g_hgh[b * HIDD + tid]       = __float2half_rn(a0 * inv);
    g_hgh[b * HIDD + 256 + tid] = __float2half_rn(a1 * inv);
    g_hgh[b * HIDD + 512 + tid] = __float2half_rn(a2 * inv);
}

// ---------------- launch ----------------
extern "C" void kernel_launch(void* const* d_in, const int* in_sizes, int n_in,
                              void* d_out, int out_size)
{
    const float* x       = (const float*)d_in[0];
    const int*   ei      = (const int*)d_in[1];
    const int*   batch   = (const int*)d_in[2];
    const float* W       = (const float*)d_in[3];
    const float* att_src = (const float*)d_in[4];
    const float* att_dst = (const float*)d_in[5];
    const float* bias    = (const float*)d_in[6];
    const float* gamma   = (const float*)d_in[7];
    const float* beta    = (const float*)d_in[8];
    const float* out_w   = (const float*)d_in[9];
    const float* out_b   = (const float*)d_in[10];
    float* out = (float*)d_out;

    const int* srcE = ei;
    const int* dstE = ei + Ee;

    void *p_xwh, *p_wth, *p_owh, *p_as, *p_ad;
    cudaGetSymbolAddress(&p_xwh, g_xwh);
    cudaGetSymbolAddress(&p_wth, g_wth);
    cudaGetSymbolAddress(&p_owh, g_owh);
    cudaGetSymbolAddress(&p_as,  g_asrc);
    cudaGetSymbolAddress(&p_ad,  g_adst);
    __half* xwh_ptr = (__half*)p_xwh;
    __half* wth_ptr = (__half*)p_wth;
    __half* owh_ptr = (__half*)p_owh;
    float* as0 = (float*)p_as;
    float* as1 = as0 + Nn * Hh;
    float* ad0 = (float*)p_ad;
    float* ad1 = ad0 + Nn * Hh;

    static cudaStream_t s2 = nullptr;
    static cudaEvent_t evFork = nullptr, evJoin = nullptr, evW0 = nullptr;
    if (!s2) {
        cudaStreamCreateWithFlags(&s2, cudaStreamNonBlocking);
        cudaEventCreateWithFlags(&evFork, cudaEventDisableTiming);
        cudaEventCreateWithFlags(&evJoin, cudaEventDisableTiming);
        cudaEventCreateWithFlags(&evW0, cudaEventDisableTiming);
    }

    cudaFuncSetAttribute(gemm_mma_kernel,
                         cudaFuncAttributeMaxDynamicSharedMemorySize, GEMM_SMEM);
    cudaFuncSetAttribute(gemm_out_kernel,
                         cudaFuncAttributeMaxDynamicSharedMemorySize, GEMM_SMEM);

    const int warpBlocks = Nn / 8;
    const unsigned cpBlocks = (unsigned)(((size_t)Nn * HIDD / 4 + 255) / 256);
    dim3 gemm_grid(HIDD / 128, Nn / 128);

    cudaEventRecord(evFork, 0);

    // side stream: layer-0 W prep FIRST (gates GEMM0), then CSR build + other preps
    cudaStreamWaitEvent(s2, evFork, 0);
    wt_prep_kernel<<<(HIDD * HIDD + 255) / 256, 256, 0, s2>>>(W, wth_ptr, HIDD * HIDD);
    cudaEventRecord(evW0, s2);
    deg_init_kernel<<<Nn / 256, 256, 0, s2>>>();
    deg_count_kernel<<<Ee / 256, 256, 0, s2>>>(dstE);
    scanA_kernel<<<64, 1024, 0, s2>>>();
    scanB_kernel<<<1, 64, 0, s2>>>();
    scanC_kernel<<<64, 1024, 0, s2>>>();
    fill_kernel<<<(E2 + 255) / 256, 256, 0, s2>>>(srcE, dstE);
    wt_prep_kernel<<<(HIDD * HIDD + 255) / 256, 256, 0, s2>>>(
        W + (size_t)HIDD * HIDD, wth_ptr + (size_t)HIDD * HIDD, HIDD * HIDD);
    wt_prep_kernel<<<(HIDD * HIDD + 255) / 256, 256, 0, s2>>>(out_w, owh_ptr, HIDD * HIDD);
    zero_alpha_kernel<<<Nn / 256, 256, 0, s2>>>(1);
    cudaEventRecord(evJoin, s2);

    // main stream: h init + zero alpha0, then GEMM0 (gated by evW0)
    copy_x_split_kernel<<<cpBlocks, 256>>>(x);
    zero_alpha_kernel<<<Nn / 256, 256>>>(0);
    cudaStreamWaitEvent(0, evW0, 0);
    gemm_mma_kernel<<<gemm_grid, 256, GEMM_SMEM>>>(wth_ptr, xwh_ptr,
                                                   att_src, att_dst, as0, ad0);

    // join side stream before agg0 (needs CSR) / GEMM1 (needs W1) / agg1 (needs zero1)
    cudaStreamWaitEvent(0, evJoin, 0);

    // layer-0 fused aggregation
    agg_fused_kernel<<<warpBlocks, 256>>>(bias, gamma, beta, as0, ad0, xwh_ptr);

    // layer 1
    gemm_mma_kernel<<<gemm_grid, 256, GEMM_SMEM>>>(
        wth_ptr + (size_t)HIDD * HIDD, xwh_ptr,
        att_src + Hh * Dd, att_dst + Hh * Dd, as1, ad1);
    agg_fused_kernel<<<warpBlocks, 256>>>(bias + HIDD, gamma + HIDD, beta + HIDD,
                                          as1, ad1, xwh_ptr);

    // pool + tensor-core output projection
    pool_kernel<<<Bb, 256>>>(batch);
    dim3 gridf(HIDD / 128, Bb / 128);
    gemm_out_kernel<<<gridf, 256, GEMM_SMEM>>>(out, out_b);
}

// round 15
// speedup vs baseline: 1.0250x; 1.0250x over previous
#include <cuda_runtime.h>
#include <cuda_bf16.h>
#include <cuda_fp16.h>
#include <math.h>
#include <stdint.h>

#define Nn   65536
#define Ee   262144
#define Bb   2048
#define Hh   4
#define Dd   192
#define HIDD 768
#define Ll   2
#define E2   (Ee + Nn)
#define EPSC 1e-5f
#define SLOPE 0.2f

// ---------------- scratch (no allocations allowed) ----------------
__device__ __align__(128) __half g_hh[(size_t)Nn * HIDD];    // running node feats, fp16
__device__ __align__(128) __half g_xwh[(size_t)Nn * HIDD];   // projected feats, fp16
__device__ __align__(16) float g_asrc[2][Nn * Hh];
__device__ __align__(16) float g_adst[2][Nn * Hh];
__device__ int   g_cnt[Nn];
__device__ int   g_rowptr[Nn + 1];
__device__ int   g_cursor[Nn];
__device__ int   g_srcs[E2];
__device__ int   g_blk[64];
__device__ int   g_blkoff[64];
__device__ __align__(128) __half g_hgh[Bb * HIDD];
__device__ __align__(128) __half g_wth[(size_t)Ll * HIDD * HIDD];
__device__ __align__(128) __half g_owh[(size_t)HIDD * HIDD];

// ================= helpers =================
__device__ __forceinline__ uint32_t smem_to_u32(const void* smem_ptr) {
    uint32_t addr;
    asm("{ .reg .u64 tmp; cvta.to.shared.u64 tmp, %1; cvt.u32.u64 %0, tmp; }"
        : "=r"(addr) : "l"(smem_ptr));
    return addr;
}
__device__ __forceinline__ void ldsm_x4(uint32_t* r, uint32_t addr) {
    asm volatile("ldmatrix.sync.aligned.m8n8.x4.shared.b16 {%0,%1,%2,%3}, [%4];"
        : "=r"(r[0]), "=r"(r[1]), "=r"(r[2]), "=r"(r[3]) : "r"(addr));
}
__device__ __forceinline__ void mma_f16(float* c, const uint32_t* a, const uint32_t* b) {
    asm volatile("mma.sync.aligned.m16n8k16.row.col.f32.f16.f16.f32 "
        "{%0,%1,%2,%3},{%4,%5,%6,%7},{%8,%9},{%0,%1,%2,%3};"
        : "+f"(c[0]), "+f"(c[1]), "+f"(c[2]), "+f"(c[3])
        : "r"(a[0]), "r"(a[1]), "r"(a[2]), "r"(a[3]), "r"(b[0]), "r"(b[1]));
}
__device__ __forceinline__ void cp16(uint32_t saddr, const void* gaddr) {
    asm volatile("cp.async.cg.shared.global [%0], [%1], 16;" :: "r"(saddr), "l"(gaddr));
}
__device__ __forceinline__ uint32_t pack_half2(float a, float b) {
    __half ha = __float2half_rn(a), hb = __float2half_rn(b);
    return ((uint32_t)__half_as_ushort(hb) << 16) | __half_as_ushort(ha);
}

// ---------------- init: h = fp16(x) ----------------
__global__ void copy_x_split_kernel(const float* __restrict__ x) {
    size_t i = (size_t)blockIdx.x * blockDim.x + threadIdx.x;
    size_t n4 = (size_t)Nn * HIDD / 4;
    if (i >= n4) return;
    float4 v = ((const float4*)x)[i];
    uint2 hv;
    hv.x = pack_half2(v.x, v.y);
    hv.y = pack_half2(v.z, v.w);
    ((uint2*)g_hh)[i] = hv;
}

__global__ void deg_init_kernel() {
    int i = blockIdx.x * blockDim.x + threadIdx.x;
    if (i < Nn) g_cnt[i] = 1;   // self loop
}

// zero BOTH alpha buffers
__global__ void zero_alpha_kernel() {
    int i = blockIdx.x * blockDim.x + threadIdx.x;
    if (i < 2 * Nn) {
        float4 z = make_float4(0.f, 0.f, 0.f, 0.f);
        ((float4*)g_asrc)[i] = z;
        ((float4*)g_adst)[i] = z;
    }
}

__global__ void deg_count_kernel(const int* __restrict__ dstE) {
    int e = blockIdx.x * blockDim.x + threadIdx.x;
    if (e < Ee) atomicAdd(&g_cnt[dstE[e]], 1);
}

// ---------------- parallel scan: 3 tiny kernels ----------------
__global__ void scanA_kernel() {
    int tid = threadIdx.x;
    int i = blockIdx.x * 1024 + tid;
    int v = g_cnt[i];
    int lane = tid & 31, w = tid >> 5;
    int x = v;
    #pragma unroll
    for (int o = 1; o < 32; o <<= 1) {
        int y = __shfl_up_sync(0xffffffffu, x, o);
        if (lane >= o) x += y;
    }
    __shared__ int ws[32];
    if (lane == 31) ws[w] = x;
    __syncthreads();
    if (w == 0) {
        int s = ws[lane];
        #pragma unroll
        for (int o = 1; o < 32; o <<= 1) {
            int y = __shfl_up_sync(0xffffffffu, s, o);
            if (lane >= o) s += y;
        }
        ws[lane] = s;
    }
    __syncthreads();
    int incl = x + (w ? ws[w - 1] : 0);
    g_rowptr[i] = incl - v;
    if (tid == 1023) g_blk[blockIdx.x] = incl;
}
__global__ void scanB_kernel() {
    int tid = threadIdx.x;   // 64 threads
    int v = g_blk[tid];
    __shared__ int sh[64];
    sh[tid] = v;
    __syncthreads();
    for (int o = 1; o < 64; o <<= 1) {
        int t = (tid >= o) ? sh[tid - o] : 0;
        __syncthreads();
        sh[tid] += t;
        __syncthreads();
    }
    g_blkoff[tid] = sh[tid] - v;
    if (tid == 63) g_rowptr[Nn] = E2;
}
__global__ void scanC_kernel() {
    int i = blockIdx.x * 1024 + threadIdx.x;
    int r = g_rowptr[i] + g_blkoff[blockIdx.x];
    g_rowptr[i] = r;
    g_cursor[i] = r;
}

__global__ void fill_kernel(const int* __restrict__ srcE, const int* __restrict__ dstE) {
    int e = blockIdx.x * blockDim.x + threadIdx.x;
    if (e < Ee) {
        int d = dstE[e];
        int p = atomicAdd(&g_cursor[d], 1);
        g_srcs[p] = srcE[e];
    } else if (e < E2) {
        int i = e - Ee;
        int p = atomicAdd(&g_cursor[i], 1);
        g_srcs[p] = i;   // self loop
    }
}

// W -> fp16, transposed per HIDDxHIDD block: [k][n] -> [n][k]
__global__ void wt_prep_kernel(const float* __restrict__ W, __half* __restrict__ dst,
                               int total) {
    int i = blockIdx.x * blockDim.x + threadIdx.x;
    if (i >= total) return;
    int l = i / (HIDD * HIDD);
    int r = i % (HIDD * HIDD);
    int k = r / HIDD;
    int n = r % HIDD;
    dst[((size_t)l * HIDD + n) * HIDD + k] = __float2half_rn(W[i]);
}

// ---------------- fp16 tensor-core GEMM + fused alpha, fp16 C ----------------
#define KCH   96
#define ROWE  104
#define TILE_B (128 * ROWE * 2)             // 26624
#define GEMM_SMEM (2 * 2 * TILE_B)          // 106496 B

__device__ __forceinline__ void load_chunk(
    const __half* const* srcs, uint32_t sbase, int ch, int s, int tid)
{
    int kb = ch * KCH;
    #pragma unroll
    for (int t = 0; t < 2; t++) {
        const char* src = (const char*)srcs[t] + (size_t)kb * 2;
        uint32_t dstb = sbase + (uint32_t)(s * 2 + t) * TILE_B;
        #pragma unroll
        for (int it = 0; it < 6; it++) {
            int idx = it * 256 + tid;
            int row = idx / 12;
            int c   = idx % 12;
            uint32_t sa = dstb + row * (ROWE * 2) + c * 16;
            const char* ga = src + (size_t)row * (HIDD * 2) + c * 16;
            cp16(sa, ga);
        }
    }
    asm volatile("cp.async.commit_group;" ::: "memory");
}

__global__ void __launch_bounds__(256, 2) gemm_mma_kernel(
    const __half* __restrict__ Bh_l,
    __half* __restrict__ C,
    const float* __restrict__ asv, const float* __restrict__ adv,
    float* __restrict__ gas, float* __restrict__ gad)
{
    extern __shared__ __half smem[];
    const int tid = threadIdx.x;
    const int wid = tid >> 5, lane = tid & 31;
    const int m0 = blockIdx.y * 128, n0 = blockIdx.x * 128;
    const int wm = (wid >> 2) * 64;
    const int wn = (wid & 3) * 32;
    uint32_t sbase = smem_to_u32(smem);

    const __half* srcs[2] = {
        g_hh + (size_t)m0 * HIDD,
        Bh_l + (size_t)n0 * HIDD };

    float acc[4][4][4];
    #pragma unroll
    for (int mi = 0; mi < 4; mi++)
        #pragma unroll
        for (int ni = 0; ni < 4; ni++)
            #pragma unroll
            for (int j = 0; j < 4; j++) acc[mi][ni][j] = 0.f;

    load_chunk(srcs, sbase, 0, 0, tid);

    uint32_t b_lrow = (lane & 7) + ((lane >> 4) << 3);
    uint32_t b_lcol = ((lane >> 3) & 1) << 3;

    for (int ch = 0; ch < 8; ch++) {
        int s = ch & 1;
        asm volatile("cp.async.wait_group 0;" ::: "memory");
        __syncthreads();
        if (ch < 7) load_chunk(srcs, sbase, ch + 1, s ^ 1, tid);

        uint32_t a_b  = sbase + (uint32_t)(s * 2 + 0) * TILE_B;
        uint32_t bh_b = sbase + (uint32_t)(s * 2 + 1) * TILE_B;

        #pragma unroll
        for (int ks = 0; ks < 6; ks++) {
            int kk = ks * 16;
            uint32_t Af[4][4], Bh4[2][4];
            uint32_t aoff = (uint32_t)(wm + (lane & 15)) * (ROWE * 2)
                          + (uint32_t)(kk + 8 * (lane >> 4)) * 2;
            uint32_t boff = (uint32_t)(wn + b_lrow) * (ROWE * 2)
                          + (uint32_t)(kk + b_lcol) * 2;
            #pragma unroll
            for (int nb = 0; nb < 2; nb++)
                ldsm_x4(Bh4[nb], bh_b + boff + nb * 16 * (ROWE * 2));
            #pragma unroll
            for (int mi = 0; mi < 4; mi++)
                ldsm_x4(Af[mi], a_b + aoff + mi * 16 * (ROWE * 2));
            #pragma unroll
            for (int mi = 0; mi < 4; mi++)
                #pragma unroll
                for (int ni = 0; ni < 4; ni++)
                    mma_f16(acc[mi][ni], Af[mi], &Bh4[ni >> 1][(ni & 1) * 2]);
        }
    }

    int gid = lane >> 2, tig = lane & 3;

    // ---- write C (fp16) ----
    #pragma unroll
    for (int mi = 0; mi < 4; mi++) {
        int r0 = m0 + wm + mi * 16 + gid;
        #pragma unroll
        for (int ni = 0; ni < 4; ni++) {
            int col = n0 + wn + ni * 8 + tig * 2;
            *(uint32_t*)&C[(size_t)r0 * HIDD + col] =
                pack_half2(acc[mi][ni][0], acc[mi][ni][1]);
            *(uint32_t*)&C[(size_t)(r0 + 8) * HIDD + col] =
                pack_half2(acc[mi][ni][2], acc[mi][ni][3]);
        }
    }

    // ---- fused alpha partials (fp32 acc) ----
    int head = (n0 + wn) / Dd;
    float as_c[4][2], ad_c[4][2];
    #pragma unroll
    for (int ni = 0; ni < 4; ni++) {
        int gc = n0 + wn + ni * 8 + tig * 2;
        as_c[ni][0] = asv[gc]; as_c[ni][1] = asv[gc + 1];
        ad_c[ni][0] = adv[gc]; ad_c[ni][1] = adv[gc + 1];
    }
    #pragma unroll
    for (int mi = 0; mi < 4; mi++) {
        #pragma unroll
        for (int half = 0; half < 2; half++) {
            float ps = 0.f, pd = 0.f;
            #pragma unroll
            for (int ni = 0; ni < 4; ni++) {
                float c0 = acc[mi][ni][half * 2 + 0];
                float c1 = acc[mi][ni][half * 2 + 1];
                ps += c0 * as_c[ni][0] + c1 * as_c[ni][1];
                pd += c0 * ad_c[ni][0] + c1 * ad_c[ni][1];
            }
            ps += __shfl_xor_sync(0xffffffffu, ps, 1);
            ps += __shfl_xor_sync(0xffffffffu, ps, 2);
            pd += __shfl_xor_sync(0xffffffffu, pd, 1);
            pd += __shfl_xor_sync(0xffffffffu, pd, 2);
            if (tig == 0) {
                int r = m0 + wm + mi * 16 + gid + half * 8;
                atomicAdd(&gas[r * Hh + head], ps);
                atomicAdd(&gad[r * Hh + head], pd);
            }
        }
    }
}

// ---------------- fp16 tensor GEMM for final projection ----------------
__global__ void __launch_bounds__(256, 2) gemm_out_kernel(
    float* __restrict__ Cout, const float* __restrict__ ob)
{
    extern __shared__ __half smem[];
    const int tid = threadIdx.x;
    const int wid = tid >> 5, lane = tid & 31;
    const int m0 = blockIdx.y * 128, n0 = blockIdx.x * 128;
    const int wm = (wid >> 2) * 64;
    const int wn = (wid & 3) * 32;
    uint32_t sbase = smem_to_u32(smem);

    const __half* srcs[2] = {
        g_hgh + (size_t)m0 * HIDD,
        g_owh + (size_t)n0 * HIDD };

    float acc[4][4][4];
    #pragma unroll
    for (int mi = 0; mi < 4; mi++)
        #pragma unroll
        for (int ni = 0; ni < 4; ni++)
            #pragma unroll
            for (int j = 0; j < 4; j++) acc[mi][ni][j] = 0.f;

    load_chunk(srcs, sbase, 0, 0, tid);

    uint32_t b_lrow = (lane & 7) + ((lane >> 4) << 3);
    uint32_t b_lcol = ((lane >> 3) & 1) << 3;

    for (int ch = 0; ch < 8; ch++) {
        int s = ch & 1;
        asm volatile("cp.async.wait_group 0;" ::: "memory");
        __syncthreads();
        if (ch < 7) load_chunk(srcs, sbase, ch + 1, s ^ 1, tid);

        uint32_t a_b  = sbase + (uint32_t)(s * 2 + 0) * TILE_B;
        uint32_t bh_b = sbase + (uint32_t)(s * 2 + 1) * TILE_B;

        #pragma unroll
        for (int ks = 0; ks < 6; ks++) {
            int kk = ks * 16;
            uint32_t Af[4][4], Bh4[2][4];
            uint32_t aoff = (uint32_t)(wm + (lane & 15)) * (ROWE * 2)
                          + (uint32_t)(kk + 8 * (lane >> 4)) * 2;
            uint32_t boff = (uint32_t)(wn + b_lrow) * (ROWE * 2)
                          + (uint32_t)(kk + b_lcol) * 2;
            #pragma unroll
            for (int nb = 0; nb < 2; nb++)
                ldsm_x4(Bh4[nb], bh_b + boff + nb * 16 * (ROWE * 2));
            #pragma unroll
            for (int mi = 0; mi < 4; mi++)
                ldsm_x4(Af[mi], a_b + aoff + mi * 16 * (ROWE * 2));
            #pragma unroll
            for (int mi = 0; mi < 4; mi++)
                #pragma unroll
                for (int ni = 0; ni < 4; ni++)
                    mma_f16(acc[mi][ni], Af[mi], &Bh4[ni >> 1][(ni & 1) * 2]);
        }
    }

    int gid = lane >> 2, tig = lane & 3;
    #pragma unroll
    for (int mi = 0; mi < 4; mi++) {
        int r0 = m0 + wm + mi * 16 + gid;
        #pragma unroll
        for (int ni = 0; ni < 4; ni++) {
            int col = n0 + wn + ni * 8 + tig * 2;
            float b0 = ob[col], b1 = ob[col + 1];
            float2 v0 = make_float2(acc[mi][ni][0] + b0, acc[mi][ni][1] + b1);
            float2 v1 = make_float2(acc[mi][ni][2] + b0, acc[mi][ni][3] + b1);
            *(float2*)&Cout[(size_t)r0 * HIDD + col] = v0;
            *(float2*)&Cout[(size_t)(r0 + 8) * HIDD + col] = v1;
        }
    }
}

__device__ __forceinline__ float leaky(float v) {
    return v > 0.f ? v : SLOPE * v;
}

// ---------------- single-pass fused GAT agg + bias + LN + ReLU + residual ----------------
// (R11 hot loop — no unroll; agg is LTS-bound, ILP doesn't help and regs hurt)
__global__ void agg_fused_kernel(const float* __restrict__ bias,
                                 const float* __restrict__ gamma,
                                 const float* __restrict__ beta,
                                 const float* __restrict__ asrc,
                                 const float* __restrict__ adstv,
                                 const __half* __restrict__ xw)
{
    int w = (blockIdx.x * blockDim.x + threadIdx.x) >> 5;
    int lane = threadIdx.x & 31;
    if (w >= Nn) return;
    int beg = g_rowptr[w];
    int end = g_rowptr[w + 1];
    float4 ad = *(const float4*)(adstv + w * 4);
    bool s0 = lane < 24;
    bool s1 = lane < 16;
    bool s2 = lane < 8;

    float d0 = 0.f, d1 = 0.f, d2 = 0.f, d3 = 0.f;
    float2 acc2[3][4];
    #pragma unroll
    for (int j = 0; j < 3; j++)
        #pragma unroll
        for (int q = 0; q < 4; q++) acc2[j][q] = make_float2(0.f, 0.f);

    for (int e = beg; e < end; e++) {
        int s = g_srcs[e];
        float4 as = *(const float4*)(asrc + s * 4);
        float w0 = __expf(leaky(as.x + ad.x));
        float w1 = __expf(leaky(as.y + ad.y));
        float w2 = __expf(leaky(as.z + ad.z));
        float w3 = __expf(leaky(as.w + ad.w));
        d0 += w0; d1 += w1; d2 += w2; d3 += w3;
        float wsel[3];
        wsel[0] = s0 ? w0 : w1;
        wsel[1] = s1 ? w1 : w2;
        wsel[2] = s2 ? w2 : w3;
        const uint4* xr = ((const uint4*)(xw + (size_t)s * HIDD)) + lane;
        #pragma unroll
        for (int j = 0; j < 3; j++) {
            uint4 v = xr[j * 32];
            float2 f0 = __half22float2(*(const __half2*)&v.x);
            float2 f1 = __half22float2(*(const __half2*)&v.y);
            float2 f2 = __half22float2(*(const __half2*)&v.z);
            float2 f3 = __half22float2(*(const __half2*)&v.w);
            float ww = wsel[j];
            acc2[j][0].x = fmaf(ww, f0.x, acc2[j][0].x);
            acc2[j][0].y = fmaf(ww, f0.y, acc2[j][0].y);
            acc2[j][1].x = fmaf(ww, f1.x, acc2[j][1].x);
            acc2[j][1].y = fmaf(ww, f1.y, acc2[j][1].y);
            acc2[j][2].x = fmaf(ww, f2.x, acc2[j][2].x);
            acc2[j][2].y = fmaf(ww, f2.y, acc2[j][2].y);
            acc2[j][3].x = fmaf(ww, f3.x, acc2[j][3].x);
            acc2[j][3].y = fmaf(ww, f3.y, acc2[j][3].y);
        }
    }

    float r0 = 1.f / d0, r1 = 1.f / d1, r2 = 1.f / d2, r3 = 1.f / d3;
    float rsel[3];
    rsel[0] = s0 ? r0 : r1;
    rsel[1] = s1 ? r1 : r2;
    rsel[2] = s2 ? r2 : r3;

    float s = 0.f, sq = 0.f;
    #pragma unroll
    for (int j = 0; j < 3; j++) {
        int fb = j * 64 + lane * 2;
        float4 b40 = ((const float4*)bias)[fb];
        float4 b41 = ((const float4*)bias)[fb + 1];
        float rr = rsel[j];
        acc2[j][0].x = fmaf(acc2[j][0].x, rr, b40.x);
        acc2[j][0].y = fmaf(acc2[j][0].y, rr, b40.y);
        acc2[j][1].x = fmaf(acc2[j][1].x, rr, b40.z);
        acc2[j][1].y = fmaf(acc2[j][1].y, rr, b40.w);
        acc2[j][2].x = fmaf(acc2[j][2].x, rr, b41.x);
        acc2[j][2].y = fmaf(acc2[j][2].y, rr, b41.y);
        acc2[j][3].x = fmaf(acc2[j][3].x, rr, b41.z);
        acc2[j][3].y = fmaf(acc2[j][3].y, rr, b41.w);
        #pragma unroll
        for (int q = 0; q < 4; q++) {
            s += acc2[j][q].x + acc2[j][q].y;
            sq = fmaf(acc2[j][q].x, acc2[j][q].x, sq);
            sq = fmaf(acc2[j][q].y, acc2[j][q].y, sq);
        }
    }
    #pragma unroll
    for (int o = 16; o; o >>= 1) {
        s  += __shfl_xor_sync(0xffffffffu, s, o);
        sq += __shfl_xor_sync(0xffffffffu, sq, o);
    }
    float mean = s * (1.f / HIDD);
    float var = sq * (1.f / HIDD) - mean * mean;
    float r = rsqrtf(var + EPSC);
    size_t base8 = (size_t)w * (HIDD / 8);
    #pragma unroll
    for (int j = 0; j < 3; j++) {
        int fb = j * 64 + lane * 2;
        size_t idx8 = base8 + j * 32 + lane;
        uint4 hprev = ((const uint4*)g_hh)[idx8];
        float2 h0 = __half22float2(*(const __half2*)&hprev.x);
        float2 h1 = __half22float2(*(const __half2*)&hprev.y);
        float2 h2 = __half22float2(*(const __half2*)&hprev.z);
        float2 h3 = __half22float2(*(const __half2*)&hprev.w);
        float4 g40 = ((const float4*)gamma)[fb];
        float4 g41 = ((const float4*)gamma)[fb + 1];
        float4 be0 = ((const float4*)beta)[fb];
        float4 be1 = ((const float4*)beta)[fb + 1];
        float y0 = fmaxf((acc2[j][0].x - mean) * r * g40.x + be0.x, 0.f) + h0.x;
        float y1 = fmaxf((acc2[j][0].y - mean) * r * g40.y + be0.y, 0.f) + h0.y;
        float y2 = fmaxf((acc2[j][1].x - mean) * r * g40.z + be0.z, 0.f) + h1.x;
        float y3 = fmaxf((acc2[j][1].y - mean) * r * g40.w + be0.w, 0.f) + h1.y;
        float y4 = fmaxf((acc2[j][2].x - mean) * r * g41.x + be1.x, 0.f) + h2.x;
        float y5 = fmaxf((acc2[j][2].y - mean) * r * g41.y + be1.y, 0.f) + h2.y;
        float y6 = fmaxf((acc2[j][3].x - mean) * r * g41.z + be1.z, 0.f) + h3.x;
        float y7 = fmaxf((acc2[j][3].y - mean) * r * g41.w + be1.w, 0.f) + h3.y;
        uint4 hv;
        hv.x = pack_half2(y0, y1);
        hv.y = pack_half2(y2, y3);
        hv.z = pack_half2(y4, y5);
        hv.w = pack_half2(y6, y7);
        ((uint4*)g_hh)[idx8] = hv;
    }
}

// ---------------- mean pool per graph (batch_vec sorted), fp16 in/out ----------------
__device__ __forceinline__ int lowerb(const int* a, int n, int key) {
    int lo = 0, hi = n;
    while (lo < hi) {
        int mid = (lo + hi) >> 1;
        if (a[mid] < key) lo = mid + 1; else hi = mid;
    }
    return lo;
}

__global__ void pool_kernel(const int* __restrict__ batch)
{
    int b = blockIdx.x;
    int tid = threadIdx.x;   // 256 threads
    __shared__ int s_beg, s_end;
    if (tid == 0) {
        s_beg = lowerb(batch, Nn, b);
        s_end = lowerb(batch, Nn, b + 1);
    }
    __syncthreads();
    int beg = s_beg, end = s_end;
    float a0 = 0.f, a1 = 0.f, a2 = 0.f;
    for (int n = beg; n < end; n++) {
        const __half* row = g_hh + (size_t)n * HIDD;
        a0 += __half2float(row[tid]);
        a1 += __half2float(row[256 + tid]);
        a2 += __half2float(row[512 + tid]);
    }
    float c = fmaxf((float)(end - beg), 1.0f);
    float inv = 1.f / c;
    g_hgh[b * HIDD + tid]       = __float2half_rn(a0 * inv);
    g_hgh[b * HIDD + 256 + tid] = __float2half_rn(a1 * inv);
    g_hgh[b * HIDD + 512 + tid] = __float2half_rn(a2 * inv);
}

// ---------------- launch ----------------
extern "C" void kernel_launch(void* const* d_in, const int* in_sizes, int n_in,
                              void* d_out, int out_size)
{
    const float* x       = (const float*)d_in[0];
    const int*   ei      = (const int*)d_in[1];
    const int*   batch   = (const int*)d_in[2];
    const float* W       = (const float*)d_in[3];
    const float* att_src = (const float*)d_in[4];
    const float* att_dst = (const float*)d_in[5];
    const float* bias    = (const float*)d_in[6];
    const float* gamma   = (const float*)d_in[7];
    const float* beta    = (const float*)d_in[8];
    const float* out_w   = (const float*)d_in[9];
    const float* out_b   = (const float*)d_in[10];
    float* out = (float*)d_out;

    const int* srcE = ei;
    const int* dstE = ei + Ee;

    void *p_xwh, *p_wth, *p_owh, *p_as, *p_ad;
    cudaGetSymbolAddress(&p_xwh, g_xwh);
    cudaGetSymbolAddress(&p_wth, g_wth);
    cudaGetSymbolAddress(&p_owh, g_owh);
    cudaGetSymbolAddress(&p_as,  g_asrc);
    cudaGetSymbolAddress(&p_ad,  g_adst);
    __half* xwh_ptr = (__half*)p_xwh;
    __half* wth_ptr = (__half*)p_wth;
    __half* owh_ptr = (__half*)p_owh;
    float* as0 = (float*)p_as;
    float* as1 = as0 + Nn * Hh;
    float* ad0 = (float*)p_ad;
    float* ad1 = ad0 + Nn * Hh;

    static cudaStream_t s2 = nullptr;
    static cudaEvent_t evFork = nullptr, evJoin = nullptr, evX = nullptr;
    if (!s2) {
        cudaStreamCreateWithFlags(&s2, cudaStreamNonBlocking);
        cudaEventCreateWithFlags(&evFork, cudaEventDisableTiming);
        cudaEventCreateWithFlags(&evJoin, cudaEventDisableTiming);
        cudaEventCreateWithFlags(&evX, cudaEventDisableTiming);
    }

    cudaFuncSetAttribute(gemm_mma_kernel,
                         cudaFuncAttributeMaxDynamicSharedMemorySize, GEMM_SMEM);
    cudaFuncSetAttribute(gemm_out_kernel,
                         cudaFuncAttributeMaxDynamicSharedMemorySize, GEMM_SMEM);

    const int warpBlocks = Nn / 8;
    const unsigned cpBlocks = (unsigned)(((size_t)Nn * HIDD / 4 + 255) / 256);
    dim3 gemm_grid(HIDD / 128, Nn / 128);

    cudaEventRecord(evFork, 0);

    // side stream: copy_x FIRST (gates GEMM0), then CSR build + other W preps
    cudaStreamWaitEvent(s2, evFork, 0);
    copy_x_split_kernel<<<cpBlocks, 256, 0, s2>>>(x);
    cudaEventRecord(evX, s2);
    deg_init_kernel<<<Nn / 256, 256, 0, s2>>>();
    deg_count_kernel<<<Ee / 256, 256, 0, s2>>>(dstE);
    scanA_kernel<<<64, 1024, 0, s2>>>();
    scanB_kernel<<<1, 64, 0, s2>>>();
    scanC_kernel<<<64, 1024, 0, s2>>>();
    fill_kernel<<<(E2 + 255) / 256, 256, 0, s2>>>(srcE, dstE);
    wt_prep_kernel<<<(HIDD * HIDD + 255) / 256, 256, 0, s2>>>(
        W + (size_t)HIDD * HIDD, wth_ptr + (size_t)HIDD * HIDD, HIDD * HIDD);
    wt_prep_kernel<<<(HIDD * HIDD + 255) / 256, 256, 0, s2>>>(out_w, owh_ptr, HIDD * HIDD);
    cudaEventRecord(evJoin, s2);

    // main stream: layer-0 W prep + zero alphas (concurrent with copy_x), then GEMM0
    wt_prep_kernel<<<(HIDD * HIDD + 255) / 256, 256>>>(W, wth_ptr, HIDD * HIDD);
    zero_alpha_kernel<<<2 * Nn / 256, 256>>>();
    cudaStreamWaitEvent(0, evX, 0);
    gemm_mma_kernel<<<gemm_grid, 256, GEMM_SMEM>>>(wth_ptr, xwh_ptr,
                                                   att_src, att_dst, as0, ad0);

    // join side stream before agg0 (needs CSR) / GEMM1 (needs W1)
    cudaStreamWaitEvent(0, evJoin, 0);

    // layer-0 fused aggregation
    agg_fused_kernel<<<warpBlocks, 256>>>(bias, gamma, beta, as0, ad0, xwh_ptr);

    // layer 1
    gemm_mma_kernel<<<gemm_grid, 256, GEMM_SMEM>>>(
        wth_ptr + (size_t)HIDD * HIDD, xwh_ptr,
        att_src + Hh * Dd, att_dst + Hh * Dd, as1, ad1);
    agg_fused_kernel<<<warpBlocks, 256>>>(bias + HIDD, gamma + HIDD, beta + HIDD,
                                          as1, ad1, xwh_ptr);

    // pool + tensor-core output projection
    pool_kernel<<<Bb, 256>>>(batch);
    dim3 gridf(HIDD / 128, Bb / 128);
    gemm_out_kernel<<<gridf, 256, GEMM_SMEM>>>(out, out_b);
}